// round 2
// baseline (speedup 1.0000x reference)
#include <cuda_runtime.h>
#include <cstdint>

#define BATCH 4
#define NPTS  4096
#define NSAMP 1024
#define KNB   32
#define NCENT 4096          // BATCH*NSAMP
#define NPCOL 131072        // NCENT*KNB

// ---------------- scratch (static device memory: allowed) ----------------
__device__ int   g_cent[NCENT];
__device__ int   g_knn[NCENT * KNB];
__device__ float g_w12[256 * 6];
__device__ float g_h2[(size_t)256 * NPCOL];   // 128 MB (conv2 pre-activation; reused as conv4 output)
__device__ float g_xm[256 * NCENT];           // 4 MB
__device__ float g_h3[(size_t)512 * NPCOL];   // 256 MB
__device__ float g_sum[512], g_sq[512];
__device__ float g_s2[256], g_t2[256];
__device__ float g_s3[512], g_t3[512];
__device__ float g_s4[256], g_t4[256];

// ---------------- helpers ----------------
__device__ __forceinline__ unsigned fkey(float x) {
    unsigned u = __float_as_uint(x);
    // monotone map float -> uint (handles tiny negatives from cancellation)
    u ^= (u & 0x80000000u) ? 0xFFFFFFFFu : 0x80000000u;
    return u;
}

// ---------------- FPS: one block per batch, sequential argmax ----------------
__global__ void fps_kernel(const float* __restrict__ p, float* __restrict__ out)
{
    extern __shared__ float sm[];
    float* sx = sm;
    float* sy = sm + NPTS;
    float* sz = sm + 2 * NPTS;
    __shared__ unsigned long long wmax[32];
    __shared__ float cc[3];

    int b = blockIdx.x, t = threadIdx.x;
    const float* pb = p + (size_t)b * NPTS * 3;
    for (int i = t; i < NPTS; i += 1024) {
        sx[i] = pb[3 * i]; sy[i] = pb[3 * i + 1]; sz[i] = pb[3 * i + 2];
    }
    float dmin[4];
#pragma unroll
    for (int j = 0; j < 4; j++) dmin[j] = 1e10f;
    __syncthreads();
    if (t == 0) {
        g_cent[b * NSAMP] = 0;
        out[(size_t)(b * NSAMP) * 3 + 0] = sx[0];
        out[(size_t)(b * NSAMP) * 3 + 1] = sy[0];
        out[(size_t)(b * NSAMP) * 3 + 2] = sz[0];
        cc[0] = sx[0]; cc[1] = sy[0]; cc[2] = sz[0];
    }
    __syncthreads();

    int lane = t & 31, warp = t >> 5;
    for (int it = 1; it < NSAMP; it++) {
        float cx = cc[0], cy = cc[1], cz = cc[2];
        unsigned long long best = 0ull;
#pragma unroll
        for (int j = 0; j < 4; j++) {
            int i = t + j * 1024;
            float dx = __fsub_rn(sx[i], cx);
            float dy = __fsub_rn(sy[i], cy);
            float dz = __fsub_rn(sz[i], cz);
            float d = __fadd_rn(__fadd_rn(__fmul_rn(dx, dx), __fmul_rn(dy, dy)), __fmul_rn(dz, dz));
            dmin[j] = fminf(dmin[j], d);
            unsigned long long key =
                ((unsigned long long)__float_as_uint(dmin[j]) << 32) | (unsigned)(~i);
            best = key > best ? key : best;
        }
#pragma unroll
        for (int o = 16; o; o >>= 1) {
            unsigned long long v = __shfl_xor_sync(0xFFFFFFFFu, best, o);
            best = v > best ? v : best;
        }
        if (lane == 0) wmax[warp] = best;
        __syncthreads();
        if (warp == 0) {
            best = wmax[lane];
#pragma unroll
            for (int o = 16; o; o >>= 1) {
                unsigned long long v = __shfl_xor_sync(0xFFFFFFFFu, best, o);
                best = v > best ? v : best;
            }
            if (lane == 0) {
                int idx = (int)(~(unsigned)(best & 0xFFFFFFFFull));
                g_cent[b * NSAMP + it] = idx;
                size_t o3 = (size_t)(b * NSAMP + it) * 3;
                out[o3 + 0] = sx[idx]; out[o3 + 1] = sy[idx]; out[o3 + 2] = sz[idx];
                cc[0] = sx[idx]; cc[1] = sy[idx]; cc[2] = sz[idx];
            }
        }
        __syncthreads();
    }
}

// ---------------- KNN: 32 blocks/batch, 8 warps/block, 4 centroids/warp ----------------
__global__ void knn_kernel(const float* __restrict__ p)
{
    extern __shared__ float sm[];
    float* sx = sm;
    float* sy = sm + NPTS;
    float* sz = sm + 2 * NPTS;

    int b = blockIdx.x >> 5;
    int blk = blockIdx.x & 31;
    const float* pb = p + (size_t)b * NPTS * 3;
    int t = threadIdx.x;
    for (int i = t; i < NPTS; i += 256) {
        sx[i] = pb[3 * i]; sy[i] = pb[3 * i + 1]; sz[i] = pb[3 * i + 2];
    }
    __syncthreads();
    int warp = t >> 5, lane = t & 31;

    for (int q = 0; q < 4; q++) {
        int sc = (blk * 8 + warp) * 4 + q;     // centroid index within batch
        int ci = g_cent[b * NSAMP + sc];
        float cx = sx[ci], cy = sy[ci], cz = sz[ci];
        float normc = __fadd_rn(__fadd_rn(__fmul_rn(cx, cx), __fmul_rn(cy, cy)), __fmul_rn(cz, cz));

        auto makekey = [&](int j) -> unsigned long long {
            float px = sx[j], py = sy[j], pz = sz[j];
            float normp = __fadd_rn(__fadd_rn(__fmul_rn(px, px), __fmul_rn(py, py)), __fmul_rn(pz, pz));
            float dot = __fadd_rn(__fadd_rn(__fmul_rn(cx, px), __fmul_rn(cy, py)), __fmul_rn(cz, pz));
            float d2 = __fsub_rn(__fadd_rn(normc, normp), __fmul_rn(2.0f, dot));
            return ((unsigned long long)fkey(d2) << 32) | (unsigned)j;
        };

        unsigned long long best = makekey(lane);
        unsigned long long thresh;
        {
            unsigned long long mv = best;
#pragma unroll
            for (int o = 16; o; o >>= 1) {
                unsigned long long v = __shfl_xor_sync(0xFFFFFFFFu, mv, o);
                mv = v > mv ? v : mv;
            }
            thresh = mv;
        }
        for (int chunk = 1; chunk < NPTS / 32; chunk++) {
            unsigned long long cand = makekey(chunk * 32 + lane);
            unsigned mask = __ballot_sync(0xFFFFFFFFu, cand < thresh);
            while (mask) {
                int src = __ffs(mask) - 1;
                mask &= mask - 1;
                unsigned long long v = __shfl_sync(0xFFFFFFFFu, cand, src);
                // warp argmax of current top-32 set (keys unique -> consistent winner)
                unsigned long long mv = best; int ml = lane;
#pragma unroll
                for (int o = 16; o; o >>= 1) {
                    unsigned long long ov = __shfl_xor_sync(0xFFFFFFFFu, mv, o);
                    int ol = __shfl_xor_sync(0xFFFFFFFFu, ml, o);
                    if (ov > mv) { mv = ov; ml = ol; }
                }
                if (v < mv && lane == ml) best = v;
                thresh = mv;   // conservative (>= true current max)
            }
        }
        g_knn[(size_t)(b * NSAMP + sc) * KNB + lane] = (int)(unsigned)(best & 0xFFFFFFFFull);
    }
}

// ---------------- w12 = w2 @ w1 (256x6) ----------------
__global__ void w12_kernel(const float* __restrict__ w1, const float* __restrict__ w2)
{
    int o = threadIdx.x;
    float acc[6] = {0, 0, 0, 0, 0, 0};
    for (int m = 0; m < 256; m++) {
        float wm = w2[o * 256 + m];
#pragma unroll
        for (int j = 0; j < 6; j++) acc[j] = fmaf(wm, w1[m * 6 + j], acc[j]);
    }
#pragma unroll
    for (int j = 0; j < 6; j++) g_w12[o * 6 + j] = acc[j];
}

// ---------------- stage1: gather + fused conv1+conv2 -> h2 ----------------
__global__ void stage1_kernel(const float* __restrict__ p, const float* __restrict__ f,
                              const float* __restrict__ b2)
{
    __shared__ float x0s[6][KNB];
    __shared__ float ws[256 * 6 + 256];
    int pt = blockIdx.x;            // b*NSAMP + s
    int b = pt >> 10;
    int t = threadIdx.x;
    for (int i = t; i < 256 * 6 + 256; i += 256)
        ws[i] = (i < 1536) ? g_w12[i] : b2[i - 1536];
    if (t < KNB) {
        int idx = g_knn[(size_t)pt * KNB + t];
        const float* pp = p + (size_t)(b * NPTS + idx) * 3;
        x0s[0][t] = pp[0]; x0s[1][t] = pp[1]; x0s[2][t] = pp[2];
        x0s[3][t] = f[(size_t)(b * 3 + 0) * NPTS + idx];
        x0s[4][t] = f[(size_t)(b * 3 + 1) * NPTS + idx];
        x0s[5][t] = f[(size_t)(b * 3 + 2) * NPTS + idx];
    }
    __syncthreads();
    int k = t & 31, cg = t >> 5;   // 8 channel groups x 32 k
    float v0 = x0s[0][k], v1 = x0s[1][k], v2 = x0s[2][k],
          v3 = x0s[3][k], v4 = x0s[4][k], v5 = x0s[5][k];
#pragma unroll 4
    for (int m = 0; m < 32; m++) {
        int c = cg * 32 + m;
        float acc = ws[1536 + c];
        acc = fmaf(ws[c * 6 + 0], v0, acc);
        acc = fmaf(ws[c * 6 + 1], v1, acc);
        acc = fmaf(ws[c * 6 + 2], v2, acc);
        acc = fmaf(ws[c * 6 + 3], v3, acc);
        acc = fmaf(ws[c * 6 + 4], v4, acc);
        acc = fmaf(ws[c * 6 + 5], v5, acc);
        g_h2[(size_t)c * NPCOL + (size_t)pt * KNB + k] = acc;
    }
}

// ---------------- BN stats: one block per channel ----------------
__global__ void bnstats_kernel(int which)
{
    const float* src = (which == 1) ? g_h3 : g_h2;   // which 0 -> h2, 1 -> h3, 2 -> h4 (in g_h2)
    int c = blockIdx.x;
    int t = threadIdx.x;
    const float4* row = (const float4*)(src + (size_t)c * NPCOL);
    float s = 0.f, q = 0.f;
    for (int i = t; i < NPCOL / 4; i += 256) {
        float4 v = row[i];
        s += v.x + v.y + v.z + v.w;
        q += v.x * v.x + v.y * v.y + v.z * v.z + v.w * v.w;
    }
    __shared__ float rs[256], rq[256];
    rs[t] = s; rq[t] = q;
    __syncthreads();
    for (int o = 128; o; o >>= 1) {
        if (t < o) { rs[t] += rs[t + o]; rq[t] += rq[t + o]; }
        __syncthreads();
    }
    if (t == 0) { g_sum[c] = rs[0]; g_sq[c] = rq[0]; }
}

__global__ void bnfinal_kernel(int which, int n, const float* __restrict__ g,
                               const float* __restrict__ be)
{
    int c = blockIdx.x * blockDim.x + threadIdx.x;
    if (c >= n) return;
    float inv = 1.0f / (float)NPCOL;
    float mean = g_sum[c] * inv;
    float var  = g_sq[c] * inv - mean * mean;
    float s = g[c] * rsqrtf(var + 1e-5f);
    float tt = be[c] - mean * s;
    if (which == 0) { g_s2[c] = s; g_t2[c] = tt; }
    else if (which == 1) { g_s3[c] = s; g_t3[c] = tt; }
    else { g_s4[c] = s; g_t4[c] = tt; }
}

// ---------------- xm = max_k relu(bn2(h2)) ----------------
__global__ void xm_kernel()
{
    int gid = blockIdx.x * 256 + threadIdx.x;      // 256 * 4096
    int c = gid >> 12, pt = gid & 4095;
    float s = g_s2[c], t = g_t2[c];
    const float4* src = (const float4*)(g_h2 + (size_t)c * NPCOL + (size_t)pt * KNB);
    float m = 0.f;   // relu floor
#pragma unroll
    for (int i = 0; i < 8; i++) {
        float4 v = src[i];
        m = fmaxf(m, fmaxf(fmaxf(fmaf(v.x, s, t), fmaf(v.y, s, t)),
                           fmaxf(fmaf(v.z, s, t), fmaf(v.w, s, t))));
    }
    g_xm[c * NCENT + pt] = m;
}

// ---------------- GEMM: C = W @ Xin (Xin built on the fly) ----------------
// mode 0: conv3  C(512 x NPCOL) = w3(512x512) @ [xm ; relu(bn2(h2))]  -> g_h3
// mode 1: conv4  C(256 x NPCOL) = w4(256x512) @ relu(bn3(h3))         -> g_h2 (reuse)
#define BM 128
#define BNN 128
#define BK 16
__global__ __launch_bounds__(256, 2) void gemm_kernel(int mode, const float* __restrict__ W)
{
    __shared__ __align__(16) float As[BK][BM];
    __shared__ __align__(16) float Bs[BK][BNN];
    int n0 = blockIdx.x * BNN;
    int m0 = blockIdx.y * BM;
    int tid = threadIdx.x;
    int tx = tid & 15, ty = tid >> 4;
    float acc[8][8];
#pragma unroll
    for (int i = 0; i < 8; i++)
#pragma unroll
        for (int j = 0; j < 8; j++) acc[i][j] = 0.f;

    for (int k0 = 0; k0 < 512; k0 += BK) {
        // load A tile (transposed into As[k][m])
        {
            int m = tid >> 1, kq = (tid & 1) * 8;
            const float4* ap = (const float4*)(W + (size_t)(m0 + m) * 512 + k0 + kq);
            float4 a0 = ap[0], a1 = ap[1];
            As[kq + 0][m] = a0.x; As[kq + 1][m] = a0.y; As[kq + 2][m] = a0.z; As[kq + 3][m] = a0.w;
            As[kq + 4][m] = a1.x; As[kq + 5][m] = a1.y; As[kq + 6][m] = a1.z; As[kq + 7][m] = a1.w;
        }
        // load B tile (built on the fly)
        {
            int r = tid >> 4, c8 = (tid & 15) * 8;
            int i = k0 + r;
            if (mode == 0) {
                if (i < 256) {
                    int pt = (n0 + c8) >> 5;     // all 8 cols share one pt (8 | 32)
                    float v = g_xm[i * NCENT + pt];
#pragma unroll
                    for (int j = 0; j < 8; j++) Bs[r][c8 + j] = v;
                } else {
                    float s = g_s2[i - 256], tt = g_t2[i - 256];
                    const float4* hp = (const float4*)(g_h2 + (size_t)(i - 256) * NPCOL + n0 + c8);
                    float4 h0 = hp[0], h1 = hp[1];
                    Bs[r][c8 + 0] = fmaxf(fmaf(h0.x, s, tt), 0.f);
                    Bs[r][c8 + 1] = fmaxf(fmaf(h0.y, s, tt), 0.f);
                    Bs[r][c8 + 2] = fmaxf(fmaf(h0.z, s, tt), 0.f);
                    Bs[r][c8 + 3] = fmaxf(fmaf(h0.w, s, tt), 0.f);
                    Bs[r][c8 + 4] = fmaxf(fmaf(h1.x, s, tt), 0.f);
                    Bs[r][c8 + 5] = fmaxf(fmaf(h1.y, s, tt), 0.f);
                    Bs[r][c8 + 6] = fmaxf(fmaf(h1.z, s, tt), 0.f);
                    Bs[r][c8 + 7] = fmaxf(fmaf(h1.w, s, tt), 0.f);
                }
            } else {
                float s = g_s3[i], tt = g_t3[i];
                const float4* hp = (const float4*)(g_h3 + (size_t)i * NPCOL + n0 + c8);
                float4 h0 = hp[0], h1 = hp[1];
                Bs[r][c8 + 0] = fmaxf(fmaf(h0.x, s, tt), 0.f);
                Bs[r][c8 + 1] = fmaxf(fmaf(h0.y, s, tt), 0.f);
                Bs[r][c8 + 2] = fmaxf(fmaf(h0.z, s, tt), 0.f);
                Bs[r][c8 + 3] = fmaxf(fmaf(h0.w, s, tt), 0.f);
                Bs[r][c8 + 4] = fmaxf(fmaf(h1.x, s, tt), 0.f);
                Bs[r][c8 + 5] = fmaxf(fmaf(h1.y, s, tt), 0.f);
                Bs[r][c8 + 6] = fmaxf(fmaf(h1.z, s, tt), 0.f);
                Bs[r][c8 + 7] = fmaxf(fmaf(h1.w, s, tt), 0.f);
            }
        }
        __syncthreads();
#pragma unroll
        for (int kk = 0; kk < BK; kk++) {
            float a[8], bb[8];
            *(float4*)(&a[0]) = *(const float4*)(&As[kk][ty * 8]);
            *(float4*)(&a[4]) = *(const float4*)(&As[kk][ty * 8 + 4]);
            *(float4*)(&bb[0]) = *(const float4*)(&Bs[kk][tx * 8]);
            *(float4*)(&bb[4]) = *(const float4*)(&Bs[kk][tx * 8 + 4]);
#pragma unroll
            for (int i = 0; i < 8; i++)
#pragma unroll
                for (int j = 0; j < 8; j++)
                    acc[i][j] = fmaf(a[i], bb[j], acc[i][j]);
        }
        __syncthreads();
    }
    float* C = (mode == 0) ? g_h3 : g_h2;
#pragma unroll
    for (int i = 0; i < 8; i++) {
        int m = m0 + ty * 8 + i;
        float* cp = C + (size_t)m * NPCOL + n0 + tx * 8;
        *(float4*)cp = make_float4(acc[i][0], acc[i][1], acc[i][2], acc[i][3]);
        *(float4*)(cp + 4) = make_float4(acc[i][4], acc[i][5], acc[i][6], acc[i][7]);
    }
}

// ---------------- final: out_feat = max_k relu(bn4(h4)) ----------------
__global__ void final_kernel(float* __restrict__ out)
{
    int gid = blockIdx.x * 256 + threadIdx.x;
    int c = gid >> 12, pt = gid & 4095;
    float s = g_s4[c], t = g_t4[c];
    const float4* src = (const float4*)(g_h2 + (size_t)c * NPCOL + (size_t)pt * KNB);
    float m = 0.f;
#pragma unroll
    for (int i = 0; i < 8; i++) {
        float4 v = src[i];
        m = fmaxf(m, fmaxf(fmaxf(fmaf(v.x, s, t), fmaf(v.y, s, t)),
                           fmaxf(fmaf(v.z, s, t), fmaf(v.w, s, t))));
    }
    int b = pt >> 10, sIdx = pt & 1023;
    out[12288 + (size_t)((b << 8) + c) * 1024 + sIdx] = m;
}

// ---------------- launch ----------------
extern "C" void kernel_launch(void* const* d_in, const int* in_sizes, int n_in,
                              void* d_out, int out_size)
{
    const float* p   = (const float*)d_in[0];
    const float* f   = (const float*)d_in[1];
    const float* w1  = (const float*)d_in[2];
    const float* w2  = (const float*)d_in[3];
    const float* b2  = (const float*)d_in[4];
    const float* g2  = (const float*)d_in[5];
    const float* be2 = (const float*)d_in[6];
    const float* w3  = (const float*)d_in[7];
    const float* g3  = (const float*)d_in[8];
    const float* be3 = (const float*)d_in[9];
    const float* w4  = (const float*)d_in[10];
    const float* g4  = (const float*)d_in[11];
    const float* be4 = (const float*)d_in[12];
    float* out = (float*)d_out;

    // Opt-in shared memory (capture-safe, idempotent non-stream calls).
    cudaFuncSetAttribute(fps_kernel, cudaFuncAttributeMaxDynamicSharedMemorySize, 65536);
    cudaFuncSetAttribute(knn_kernel, cudaFuncAttributeMaxDynamicSharedMemorySize, 65536);

    w12_kernel<<<1, 256>>>(w1, w2);
    fps_kernel<<<BATCH, 1024, NPTS * 3 * sizeof(float)>>>(p, out);
    knn_kernel<<<BATCH * 32, 256, NPTS * 3 * sizeof(float)>>>(p);
    stage1_kernel<<<NCENT, 256>>>(p, f, b2);

    bnstats_kernel<<<256, 256>>>(0);
    bnfinal_kernel<<<1, 256>>>(0, 256, g2, be2);
    xm_kernel<<<NCENT, 256>>>();

    gemm_kernel<<<dim3(NPCOL / BNN, 512 / BM), 256>>>(0, w3);
    bnstats_kernel<<<512, 256>>>(1);
    bnfinal_kernel<<<2, 256>>>(1, 512, g3, be3);

    gemm_kernel<<<dim3(NPCOL / BNN, 256 / BM), 256>>>(1, w4);
    bnstats_kernel<<<256, 256>>>(2);
    bnfinal_kernel<<<1, 256>>>(2, 256, g4, be4);

    final_kernel<<<NCENT, 256>>>(out);
}